// round 10
// baseline (speedup 1.0000x reference)
#include <cuda_runtime.h>
#include <cstdint>

// GraphReversePool: out[b, v] = x[b, v2c[v]]
//   x   : [BATCH, N_CLUSTERS] fp32   (d_in[0])
//   v2c : [VERTICES] int32           (d_in[1])
//   out : [BATCH, VERTICES] fp32
//
// R9: cut the LSU floor. Stores leave the LSU: gather results go to a
// per-warp 512B smem buffer via STS.128 (4 cyc/warp vs STG.128's 12), then
// an elected lane drains it with cp.async.bulk shared->global (TMA engine,
// off the LSU path). Per-warp pipelines: no block-wide syncs, only
// __syncwarp + wait_group.read for buffer reuse.
// 960 threads/CTA so row(100000B) + 30x512B buffers fit 2 CTAs/SM.

#define BLOCK_THREADS 960   // 30 warps

__device__ __forceinline__ uint32_t smem_u32(const void* p) {
    return (uint32_t)__cvta_generic_to_shared(p);
}

__global__ __launch_bounds__(BLOCK_THREADS, 2)
void graph_reverse_pool_kernel(const float* __restrict__ x,
                               const int*   __restrict__ v2c,
                               float*       __restrict__ out,
                               int batch, int n_clusters, int n_vertices)
{
    extern __shared__ __align__(16) unsigned char smem_raw[];
    float* srow = reinterpret_cast<float*>(smem_raw);

    const int b = blockIdx.x;

    const int row_bytes = n_clusters * 4;
    const int mbar_off  = (row_bytes + 15) & ~15;
    uint64_t* mbar = reinterpret_cast<uint64_t*>(smem_raw + mbar_off);
    const uint32_t mbar_addr = smem_u32(mbar);
    unsigned char* warp_bufs = smem_raw + mbar_off + 16;   // 30 x 512B

    const float* __restrict__ xrow = x + (size_t)b * n_clusters;

    // ---- Stage x row into smem with one bulk DMA ----
    const bool can_bulk = ((row_bytes & 15) == 0) &&
                          ((((uintptr_t)xrow) & 15) == 0);
    if (can_bulk) {
        if (threadIdx.x == 0) {
            asm volatile("mbarrier.init.shared.b64 [%0], 1;"
                         :: "r"(mbar_addr) : "memory");
            asm volatile("fence.proxy.async.shared::cta;" ::: "memory");
        }
        __syncthreads();
        if (threadIdx.x == 0) {
            asm volatile("mbarrier.arrive.expect_tx.shared.b64 _, [%0], %1;"
                         :: "r"(mbar_addr), "r"((uint32_t)row_bytes) : "memory");
            asm volatile("cp.async.bulk.shared::cta.global.mbarrier::complete_tx::bytes "
                         "[%0], [%1], %2, [%3];"
                         :: "r"(smem_u32(srow)), "l"(xrow),
                            "r"((uint32_t)row_bytes), "r"(mbar_addr)
                         : "memory");
        }
        uint32_t done = 0;
        while (!done) {
            asm volatile(
                "{\n\t.reg .pred p;\n\t"
                "mbarrier.try_wait.parity.acquire.cta.shared::cta.b64 p, [%1], 0, 0x989680;\n\t"
                "selp.b32 %0, 1, 0, p;\n\t}"
                : "=r"(done) : "r"(mbar_addr) : "memory");
        }
    } else {
        for (int i = threadIdx.x; i < n_clusters; i += BLOCK_THREADS)
            srow[i] = xrow[i];
        __syncthreads();
    }

    // ---- Gather with TMA-store epilogue ----
    const int4* __restrict__ v2c4 = reinterpret_cast<const int4*>(v2c);
    float* const out_row = out + (size_t)b * n_vertices;

    const int nv4  = n_vertices >> 2;                    // 25000
    const int lane = threadIdx.x & 31;
    const int warp = threadIdx.x >> 5;
    const bool leader = (lane == 0);

    float4* mybuf = reinterpret_cast<float4*>(warp_bufs + warp * 512);
    const uint32_t mybuf_addr = smem_u32(mybuf);

    const int full = (nv4 / BLOCK_THREADS) * BLOCK_THREADS;  // 24960

    int v = threadIdx.x;
    if (v < full) {
        int4 c = v2c4[v];
        while (true) {
            const int vcur = v;
            const int vnext = v + BLOCK_THREADS;
            int4 cn;
            if (vnext < full) cn = v2c4[vnext];          // prefetch indices

            float4 a;
            a.x = srow[c.x]; a.y = srow[c.y]; a.z = srow[c.z]; a.w = srow[c.w];

            // wait until previous bulk store has READ our buffer
            if (leader) {
                asm volatile("cp.async.bulk.wait_group.read 0;" ::: "memory");
            }
            __syncwarp();
            mybuf[lane] = a;                             // STS.128
            __syncwarp();
            if (leader) {
                asm volatile("fence.proxy.async.shared::cta;" ::: "memory");
                // warp's 32 quads are contiguous: quads [vcur - lane, +32)
                float* gdst = out_row + (size_t)(vcur - lane) * 4;
                asm volatile("cp.async.bulk.global.shared::cta.bulk_group "
                             "[%0], [%1], %2;"
                             :: "l"(gdst), "r"(mybuf_addr), "r"(512u)
                             : "memory");
                asm volatile("cp.async.bulk.commit_group;" ::: "memory");
            }

            if (vnext >= full) break;
            v = vnext;
            c = cn;
        }
    }

    // tail quads [full, nv4): direct STG path
    for (int t = full + threadIdx.x; t < nv4; t += BLOCK_THREADS) {
        const int4 c = v2c4[t];
        float4 a;
        a.x = srow[c.x]; a.y = srow[c.y]; a.z = srow[c.z]; a.w = srow[c.w];
        reinterpret_cast<float4*>(out_row)[t] = a;
    }
    // scalar tail (dead for 100000, kept for safety)
    for (int t = (nv4 << 2) + threadIdx.x; t < n_vertices; t += BLOCK_THREADS) {
        out_row[t] = srow[v2c[t]];
    }

    // drain all outstanding bulk stores before exit
    if (leader) {
        asm volatile("cp.async.bulk.wait_group 0;" ::: "memory");
    }
}

extern "C" void kernel_launch(void* const* d_in, const int* in_sizes, int n_in,
                              void* d_out, int out_size)
{
    const float* x   = (const float*)d_in[0];
    const int*   v2c = (const int*)  d_in[1];
    float*       out = (float*)d_out;

    const int n_vertices = in_sizes[1];                  // 100000
    const int batch      = out_size / n_vertices;        // 1024
    const int n_clusters = in_sizes[0] / batch;          // 25000

    const int row_bytes  = n_clusters * (int)sizeof(float);          // 100000
    const int n_warps    = BLOCK_THREADS / 32;                       // 30
    const int smem_bytes = ((row_bytes + 15) & ~15) + 16 + n_warps * 512;

    static bool attr_set = false;
    if (!attr_set) {
        cudaFuncSetAttribute(graph_reverse_pool_kernel,
                             cudaFuncAttributeMaxDynamicSharedMemorySize,
                             smem_bytes);
        attr_set = true;
    }

    graph_reverse_pool_kernel<<<batch, BLOCK_THREADS, smem_bytes>>>(
        x, v2c, out, batch, n_clusters, n_vertices);
}